// round 7
// baseline (speedup 1.0000x reference)
#include <cuda_runtime.h>

#define B_  32
#define C_  128
#define CO_ 96
#define H_  64
#define W_  64
#define HW_ 4096

// ---------------- device scratch (no allocations allowed) ----------------
__device__ float  g_wsk[C_ * 9 * CO_];             // sketched weights, [ci][tap][co]
__device__ int    g_idx[3 * C_];                   // idx[j][c] = argmax_d hs[j,d,c]
__device__ float  g_med[(size_t)B_ * C_ * HW_];    // median(unsketch) result, NCHW
__device__ float2 g_sb[C_];                        // per-channel (scale, bias) for BN

// ---------------- 1) extract one-hot indices from hs ----------------
__global__ void idx_kernel(const float* __restrict__ hs) {
    int t = blockIdx.x * blockDim.x + threadIdx.x;
    if (t >= 3 * C_) return;
    int j = t >> 7, c = t & 127;
    int d = 0;
    for (int dd = 0; dd < 32; ++dd)
        if (hs[(j * 32 + dd) * C_ + c] > 0.5f) d = dd;
    g_idx[t] = d;
}

// ---------------- 2) build sketched weights: w_sk[j*32+d] = sum_{c: idx[j,c]==d} ss[j,c]*w2[c] ----
// output layout g_wsk[ci][tap][co] so each ci-chunk is a contiguous block
__global__ void wsk_kernel(const float* __restrict__ w2, const float* __restrict__ ss) {
    int e = blockIdx.x * 256 + threadIdx.x;
    if (e >= C_ * 9 * CO_) return;
    int co   = e % CO_;
    int rest = e / CO_;
    int tap  = rest % 9;
    int ci   = rest / 9;
    int j = co >> 5, d = co & 31;
    float sum = 0.f;
    for (int c = 0; c < C_; ++c) {
        int   ic = g_idx[j * C_ + c];          // uniform within warp (j,tap,ci uniform)
        float wv = w2[(c * C_ + ci) * 9 + tap];// broadcast within warp
        float sv = ss[j * C_ + c];
        sum += (ic == d) ? sv * wv : 0.f;
    }
    g_wsk[e] = sum;
}

// ---------------- 3) conv (96ch, 3x3, pad1) + unsketch + median, fused ----------------
struct SmemA { float xs[8][4][72]; float ws[8 * 9 * CO_]; };   // 9216 + 27648 = 36864 B
union  SmemU { SmemA a; float yt[CO_ * 128]; };                // 49152 B (exactly 48 KB)

__global__ __launch_bounds__(256, 2)
void conv_kernel(const float* __restrict__ x, const float* __restrict__ ss) {
    __shared__ SmemU sm;
    const int tid  = threadIdx.x;
    const int b    = blockIdx.y;
    const int h0   = blockIdx.x << 1;        // 2 output rows per CTA
    const int warp = tid >> 5, lane = tid & 31;
    const int co0  = warp * 12;              // 8 warps x 12 co = 96
    const int r    = lane >> 4;              // which of the 2 output rows
    const int w0   = (lane & 15) << 2;       // 4 consecutive w per thread

    float acc[12][4];
#pragma unroll
    for (int j = 0; j < 12; ++j)
#pragma unroll
        for (int i = 0; i < 4; ++i) acc[j][i] = 0.f;

    // zero the halo columns once (cols 0 and 65 are never overwritten by loads)
    if (tid < 64) {
        int ci = tid >> 3, rr = (tid >> 1) & 3, cp = (tid & 1) * 65;
        sm.a.xs[ci][rr][cp] = 0.f;
    }

    const float* xb = x + (size_t)b * C_ * HW_;

#pragma unroll 1
    for (int chunk = 0; chunk < 16; ++chunk) {
        const int ci0 = chunk << 3;
        __syncthreads();
        // stage x halo tile: 8 ci x 4 rows x 64 cols (coalesced), zeros outside image
#pragma unroll
        for (int k = 0; k < 8; ++k) {
            int e = tid + (k << 8);
            int ci = e >> 8, rem = e & 255, hr = rem >> 6, w = rem & 63;
            int h = h0 - 1 + hr;
            float v = ((unsigned)h < (unsigned)H_)
                        ? xb[((ci0 + ci) * H_ + h) * W_ + w] : 0.f;
            sm.a.xs[ci][hr][1 + w] = v;
        }
        // stage weights: contiguous 6912-float block (L2-resident)
        const float* gw = g_wsk + ci0 * (9 * CO_);
#pragma unroll
        for (int k = 0; k < 27; ++k)
            sm.a.ws[tid + (k << 8)] = gw[tid + (k << 8)];
        __syncthreads();

#pragma unroll 2
        for (int ci = 0; ci < 8; ++ci) {
#pragma unroll
            for (int kh = 0; kh < 3; ++kh) {
                const float* xrow = &sm.a.xs[ci][r + kh][w0];
                float4 xa = *(const float4*)xrow;       // 16B aligned
                float2 xc = *(const float2*)(xrow + 4);
                float xr[6] = {xa.x, xa.y, xa.z, xa.w, xc.x, xc.y};
#pragma unroll
                for (int kw = 0; kw < 3; ++kw) {
                    const float4* wp =
                        (const float4*)&sm.a.ws[(ci * 9 + kh * 3 + kw) * CO_ + co0];
                    float4 wv0 = wp[0], wv1 = wp[1], wv2 = wp[2];  // broadcast LDS.128
                    float wv[12] = {wv0.x, wv0.y, wv0.z, wv0.w,
                                    wv1.x, wv1.y, wv1.z, wv1.w,
                                    wv2.x, wv2.y, wv2.z, wv2.w};
#pragma unroll
                    for (int j = 0; j < 12; ++j)
#pragma unroll
                        for (int i = 0; i < 4; ++i)
                            acc[j][i] = fmaf(wv[j], xr[kw + i], acc[j][i]);
                }
            }
        }
    }

    // ---- exchange accumulators through SMEM so the unsketch is local ----
    __syncthreads();
#pragma unroll
    for (int j = 0; j < 12; ++j) {
        float4 v = make_float4(acc[j][0], acc[j][1], acc[j][2], acc[j][3]);
        *(float4*)&sm.yt[(co0 + j) * 128 + (lane << 2)] = v;
    }
    __syncthreads();

    // ---- unsketch (3-way gather + sign) + median-of-3, coalesced med store ----
    const int s  = tid & 127;            // spatial position: lanes contiguous
    const int cg = tid >> 7;             // two c-halves
    const int hh = h0 + (s >> 6);
    const int wn = s & 63;
    float* mbase = g_med + ((size_t)b * C_) * HW_ + hh * W_ + wn;
#pragma unroll 1
    for (int cc = 0; cc < 64; ++cc) {
        int c = (cg << 6) + cc;
        int i0 = g_idx[c], i1 = g_idx[C_ + c], i2 = g_idx[2 * C_ + c]; // uniform per warp
        float s0 = ss[c], s1 = ss[C_ + c], s2 = ss[2 * C_ + c];
        float v0 = s0 * sm.yt[i0 * 128 + s];          // conflict-free (s per lane)
        float v1 = s1 * sm.yt[(32 + i1) * 128 + s];
        float v2 = s2 * sm.yt[(64 + i2) * 128 + s];
        float mx = fmaxf(v0, v1), mn = fminf(v0, v1);
        float m  = fmaxf(mn, fminf(mx, v2));          // median of 3
        mbase[(size_t)c * HW_] = m;                   // coalesced across lanes
    }
}

// ---------------- 4) per-channel BN stats -> (scale, bias) ----------------
__global__ void stats_kernel(const float* __restrict__ gamma2,
                             const float* __restrict__ beta2) {
    int c = blockIdx.x;
    int tid = threadIdx.x;
    float s = 0.f, q = 0.f;
    for (int b = 0; b < B_; ++b) {
        const float* p = g_med + (size_t)(b * C_ + c) * HW_;
        for (int i = tid; i < HW_; i += 256) {
            float v = p[i];
            s += v;
            q = fmaf(v, v, q);
        }
    }
    __shared__ float rs[8], rq[8];
#pragma unroll
    for (int o = 16; o; o >>= 1) {
        s += __shfl_down_sync(0xffffffffu, s, o);
        q += __shfl_down_sync(0xffffffffu, q, o);
    }
    if ((tid & 31) == 0) { rs[tid >> 5] = s; rq[tid >> 5] = q; }
    __syncthreads();
    if (tid == 0) {
        float S = 0.f, Q = 0.f;
        for (int i = 0; i < 8; ++i) { S += rs[i]; Q += rq[i]; }
        const float invn = 1.f / (float)(B_ * HW_);
        float mean  = S * invn;
        float var   = Q * invn - mean * mean;
        float scale = gamma2[c] * rsqrtf(var + 1e-5f);
        g_sb[c] = make_float2(scale, beta2[c] - mean * scale);
    }
}

// ---------------- 5) normalize + ReLU + residual ----------------
__global__ void out_kernel(const float* __restrict__ x, float* __restrict__ out) {
    size_t i = ((size_t)blockIdx.x * 256 + threadIdx.x) << 2;
    int c = (int)((i >> 12) & 127);
    float2 sb = g_sb[c];
    float4 m  = *(const float4*)&g_med[i];
    float4 xv = *(const float4*)&x[i];
    float4 o;
    o.x = fmaxf(fmaf(m.x, sb.x, sb.y), 0.f) + xv.x;
    o.y = fmaxf(fmaf(m.y, sb.x, sb.y), 0.f) + xv.y;
    o.z = fmaxf(fmaf(m.z, sb.x, sb.y), 0.f) + xv.z;
    o.w = fmaxf(fmaf(m.w, sb.x, sb.y), 0.f) + xv.w;
    *(float4*)&out[i] = o;
}

// ---------------- launch ----------------
extern "C" void kernel_launch(void* const* d_in, const int* in_sizes, int n_in,
                              void* d_out, int out_size) {
    (void)in_sizes; (void)n_in; (void)out_size;
    const float* x      = (const float*)d_in[0];
    // d_in[1] = w1  (unused: reference discards out1)
    const float* w2     = (const float*)d_in[2];
    // d_in[3], d_in[4] = gamma1, beta1 (unused)
    const float* gamma2 = (const float*)d_in[5];
    const float* beta2  = (const float*)d_in[6];
    const float* hs     = (const float*)d_in[7];
    const float* ss     = (const float*)d_in[8];
    float* out = (float*)d_out;

    idx_kernel<<<2, 256>>>(hs);
    wsk_kernel<<<(C_ * 9 * CO_ + 255) / 256, 256>>>(w2, ss);
    conv_kernel<<<dim3(H_ / 2, B_), 256>>>(x, ss);
    stats_kernel<<<C_, 256>>>(gamma2, beta2);
    out_kernel<<<(B_ * C_ * HW_) / 1024, 256>>>(x, out);
}

// round 8
// speedup vs baseline: 1.0024x; 1.0024x over previous
#include <cuda_runtime.h>

#define B_  32
#define C_  128
#define CO_ 96
#define H_  64
#define W_  64
#define HW_ 4096

// ---------------- device scratch (no allocations allowed) ----------------
__device__ float  g_wsk[C_ * 9 * CO_];             // sketched weights, [ci][tap][co]
__device__ int    g_idx[3 * C_];                   // idx[j][c] = argmax_d hs[j,d,c]
__device__ float  g_med[(size_t)B_ * C_ * HW_];    // median(unsketch) result, NCHW
__device__ float2 g_sb[C_];                        // per-channel (scale, bias) for BN

// ---------------- 1) extract one-hot indices from hs ----------------
__global__ void idx_kernel(const float* __restrict__ hs) {
    int t = blockIdx.x * blockDim.x + threadIdx.x;
    if (t >= 3 * C_) return;
    int j = t >> 7, c = t & 127;
    int d = 0;
    for (int dd = 0; dd < 32; ++dd)
        if (hs[(j * 32 + dd) * C_ + c] > 0.5f) d = dd;
    g_idx[t] = d;
}

// ---------------- 2) build sketched weights: w_sk[j*32+d] = sum_{c: idx[j,c]==d} ss[j,c]*w2[c] ----
// output layout g_wsk[ci][tap][co] so each ci-chunk is a contiguous block
__global__ void wsk_kernel(const float* __restrict__ w2, const float* __restrict__ ss) {
    int e = blockIdx.x * 256 + threadIdx.x;
    if (e >= C_ * 9 * CO_) return;
    int co   = e % CO_;
    int rest = e / CO_;
    int tap  = rest % 9;
    int ci   = rest / 9;
    int j = co >> 5, d = co & 31;
    float sum = 0.f;
    for (int c = 0; c < C_; ++c) {
        int   ic = g_idx[j * C_ + c];          // uniform within warp (j,tap,ci uniform)
        float wv = w2[(c * C_ + ci) * 9 + tap];// broadcast within warp
        float sv = ss[j * C_ + c];
        sum += (ic == d) ? sv * wv : 0.f;
    }
    g_wsk[e] = sum;
}

// ---------------- 3) conv (96ch, 3x3, pad1) + unsketch + median, fused ----------------
struct SmemA { float xs[8][4][72]; float ws[8 * 9 * CO_]; };   // 9216 + 27648 = 36864 B
union  SmemU { SmemA a; float yt[CO_ * 128]; };                // 49152 B (exactly 48 KB)

__global__ __launch_bounds__(256, 2)
void conv_kernel(const float* __restrict__ x, const float* __restrict__ ss) {
    __shared__ SmemU sm;
    const int tid  = threadIdx.x;
    const int b    = blockIdx.y;
    const int h0   = blockIdx.x << 1;        // 2 output rows per CTA
    const int warp = tid >> 5, lane = tid & 31;
    const int co0  = warp * 12;              // 8 warps x 12 co = 96
    const int r    = lane >> 4;              // which of the 2 output rows
    const int w0   = (lane & 15) << 2;       // 4 consecutive w per thread

    float acc[12][4];
#pragma unroll
    for (int j = 0; j < 12; ++j)
#pragma unroll
        for (int i = 0; i < 4; ++i) acc[j][i] = 0.f;

    // zero the halo columns once (cols 0 and 65 are never overwritten by loads)
    if (tid < 64) {
        int ci = tid >> 3, rr = (tid >> 1) & 3, cp = (tid & 1) * 65;
        sm.a.xs[ci][rr][cp] = 0.f;
    }

    const float* xb = x + (size_t)b * C_ * HW_;

#pragma unroll 1
    for (int chunk = 0; chunk < 16; ++chunk) {
        const int ci0 = chunk << 3;
        __syncthreads();
        // stage x halo tile: 8 ci x 4 rows x 64 cols (coalesced), zeros outside image
#pragma unroll
        for (int k = 0; k < 8; ++k) {
            int e = tid + (k << 8);
            int ci = e >> 8, rem = e & 255, hr = rem >> 6, w = rem & 63;
            int h = h0 - 1 + hr;
            float v = ((unsigned)h < (unsigned)H_)
                        ? xb[((ci0 + ci) * H_ + h) * W_ + w] : 0.f;
            sm.a.xs[ci][hr][1 + w] = v;
        }
        // stage weights: contiguous 6912-float block (L2-resident)
        const float* gw = g_wsk + ci0 * (9 * CO_);
#pragma unroll
        for (int k = 0; k < 27; ++k)
            sm.a.ws[tid + (k << 8)] = gw[tid + (k << 8)];
        __syncthreads();

#pragma unroll 2
        for (int ci = 0; ci < 8; ++ci) {
#pragma unroll
            for (int kh = 0; kh < 3; ++kh) {
                const float* xrow = &sm.a.xs[ci][r + kh][w0];
                float4 xa = *(const float4*)xrow;       // 16B aligned
                float2 xc = *(const float2*)(xrow + 4);
                float xr[6] = {xa.x, xa.y, xa.z, xa.w, xc.x, xc.y};
#pragma unroll
                for (int kw = 0; kw < 3; ++kw) {
                    const float4* wp =
                        (const float4*)&sm.a.ws[(ci * 9 + kh * 3 + kw) * CO_ + co0];
                    float4 wv0 = wp[0], wv1 = wp[1], wv2 = wp[2];  // broadcast LDS.128
                    float wv[12] = {wv0.x, wv0.y, wv0.z, wv0.w,
                                    wv1.x, wv1.y, wv1.z, wv1.w,
                                    wv2.x, wv2.y, wv2.z, wv2.w};
#pragma unroll
                    for (int j = 0; j < 12; ++j)
#pragma unroll
                        for (int i = 0; i < 4; ++i)
                            acc[j][i] = fmaf(wv[j], xr[kw + i], acc[j][i]);
                }
            }
        }
    }

    // ---- exchange accumulators through SMEM so the unsketch is local ----
    __syncthreads();
#pragma unroll
    for (int j = 0; j < 12; ++j) {
        float4 v = make_float4(acc[j][0], acc[j][1], acc[j][2], acc[j][3]);
        *(float4*)&sm.yt[(co0 + j) * 128 + (lane << 2)] = v;
    }
    __syncthreads();

    // ---- unsketch (3-way gather + sign) + median-of-3, coalesced med store ----
    const int s  = tid & 127;            // spatial position: lanes contiguous
    const int cg = tid >> 7;             // two c-halves
    const int hh = h0 + (s >> 6);
    const int wn = s & 63;
    float* mbase = g_med + ((size_t)b * C_) * HW_ + hh * W_ + wn;
#pragma unroll 1
    for (int cc = 0; cc < 64; ++cc) {
        int c = (cg << 6) + cc;
        int i0 = g_idx[c], i1 = g_idx[C_ + c], i2 = g_idx[2 * C_ + c]; // uniform per warp
        float s0 = ss[c], s1 = ss[C_ + c], s2 = ss[2 * C_ + c];
        float v0 = s0 * sm.yt[i0 * 128 + s];          // conflict-free (s per lane)
        float v1 = s1 * sm.yt[(32 + i1) * 128 + s];
        float v2 = s2 * sm.yt[(64 + i2) * 128 + s];
        float mx = fmaxf(v0, v1), mn = fminf(v0, v1);
        float m  = fmaxf(mn, fminf(mx, v2));          // median of 3
        mbase[(size_t)c * HW_] = m;                   // coalesced across lanes
    }
}

// ---------------- 4) per-channel BN stats -> (scale, bias) ----------------
__global__ void stats_kernel(const float* __restrict__ gamma2,
                             const float* __restrict__ beta2) {
    int c = blockIdx.x;
    int tid = threadIdx.x;
    float s = 0.f, q = 0.f;
    for (int b = 0; b < B_; ++b) {
        const float* p = g_med + (size_t)(b * C_ + c) * HW_;
        for (int i = tid; i < HW_; i += 256) {
            float v = p[i];
            s += v;
            q = fmaf(v, v, q);
        }
    }
    __shared__ float rs[8], rq[8];
#pragma unroll
    for (int o = 16; o; o >>= 1) {
        s += __shfl_down_sync(0xffffffffu, s, o);
        q += __shfl_down_sync(0xffffffffu, q, o);
    }
    if ((tid & 31) == 0) { rs[tid >> 5] = s; rq[tid >> 5] = q; }
    __syncthreads();
    if (tid == 0) {
        float S = 0.f, Q = 0.f;
        for (int i = 0; i < 8; ++i) { S += rs[i]; Q += rq[i]; }
        const float invn = 1.f / (float)(B_ * HW_);
        float mean  = S * invn;
        float var   = Q * invn - mean * mean;
        float scale = gamma2[c] * rsqrtf(var + 1e-5f);
        g_sb[c] = make_float2(scale, beta2[c] - mean * scale);
    }
}

// ---------------- 5) normalize + ReLU + residual ----------------
__global__ void out_kernel(const float* __restrict__ x, float* __restrict__ out) {
    size_t i = ((size_t)blockIdx.x * 256 + threadIdx.x) << 2;
    int c = (int)((i >> 12) & 127);
    float2 sb = g_sb[c];
    float4 m  = *(const float4*)&g_med[i];
    float4 xv = *(const float4*)&x[i];
    float4 o;
    o.x = fmaxf(fmaf(m.x, sb.x, sb.y), 0.f) + xv.x;
    o.y = fmaxf(fmaf(m.y, sb.x, sb.y), 0.f) + xv.y;
    o.z = fmaxf(fmaf(m.z, sb.x, sb.y), 0.f) + xv.z;
    o.w = fmaxf(fmaf(m.w, sb.x, sb.y), 0.f) + xv.w;
    *(float4*)&out[i] = o;
}

// ---------------- launch ----------------
extern "C" void kernel_launch(void* const* d_in, const int* in_sizes, int n_in,
                              void* d_out, int out_size) {
    (void)in_sizes; (void)n_in; (void)out_size;
    const float* x      = (const float*)d_in[0];
    // d_in[1] = w1  (unused: reference discards out1)
    const float* w2     = (const float*)d_in[2];
    // d_in[3], d_in[4] = gamma1, beta1 (unused)
    const float* gamma2 = (const float*)d_in[5];
    const float* beta2  = (const float*)d_in[6];
    const float* hs     = (const float*)d_in[7];
    const float* ss     = (const float*)d_in[8];
    float* out = (float*)d_out;

    idx_kernel<<<2, 256>>>(hs);
    wsk_kernel<<<(C_ * 9 * CO_ + 255) / 256, 256>>>(w2, ss);
    conv_kernel<<<dim3(H_ / 2, B_), 256>>>(x, ss);
    stats_kernel<<<C_, 256>>>(gamma2, beta2);
    out_kernel<<<(B_ * C_ * HW_) / 1024, 256>>>(x, out);
}

// round 10
// speedup vs baseline: 2.0140x; 2.0093x over previous
#include <cuda_runtime.h>
#include <cuda_bf16.h>
#include <cstdint>

#define B_   32
#define C_   128
#define CO_  96
#define H_   64
#define W_   64
#define HW_  4096
#define HP_  66
#define WP_  66
#define KTOT 1152   // 9 taps * 128 ci

// ---------------- device scratch (no allocations allowed) ----------------
__device__ __align__(16) __nv_bfloat16 g_xh[(size_t)B_ * HP_ * WP_ * C_]; // padded NHWC hi
__device__ __align__(16) __nv_bfloat16 g_xl[(size_t)B_ * HP_ * WP_ * C_]; // padded NHWC lo
__device__ __align__(16) __nv_bfloat16 g_wh[CO_ * KTOT];  // A hi: [co][tap*128+ci]
__device__ __align__(16) __nv_bfloat16 g_wl[CO_ * KTOT];  // A lo
__device__ int    g_idx[3 * C_];
__device__ float  g_med[(size_t)B_ * C_ * HW_];
__device__ float2 g_part[C_ * 8];
__device__ float2 g_sb[C_];

// ---------------- PTX helpers (all sm_80-era: safe for compute_103) ----------------
__device__ __forceinline__ uint32_t smem_u32(const void* p) {
    uint32_t a;
    asm("{ .reg .u64 t; cvta.to.shared.u64 t, %1; cvt.u32.u64 %0, t; }" : "=r"(a) : "l"(p));
    return a;
}
__device__ __forceinline__ void ldsm4(uint32_t* r, uint32_t addr) {
    asm volatile("ldmatrix.sync.aligned.m8n8.x4.shared.b16 {%0,%1,%2,%3}, [%4];"
        : "=r"(r[0]), "=r"(r[1]), "=r"(r[2]), "=r"(r[3]) : "r"(addr));
}
__device__ __forceinline__ void mma16816(float* d, const uint32_t* a, const uint32_t* b) {
    asm volatile("mma.sync.aligned.m16n8k16.row.col.f32.bf16.bf16.f32 "
        "{%0,%1,%2,%3}, {%4,%5,%6,%7}, {%8,%9}, {%0,%1,%2,%3};"
        : "+f"(d[0]), "+f"(d[1]), "+f"(d[2]), "+f"(d[3])
        : "r"(a[0]), "r"(a[1]), "r"(a[2]), "r"(a[3]), "r"(b[0]), "r"(b[1]));
}

// ---------------- 1) one-hot indices from hs ----------------
__global__ void idx_kernel(const float* __restrict__ hs) {
    int t = blockIdx.x * blockDim.x + threadIdx.x;
    if (t >= 3 * C_) return;
    int j = t >> 7, c = t & 127;
    int d = 0;
    for (int dd = 0; dd < 32; ++dd)
        if (hs[(j * 32 + dd) * C_ + c] > 0.5f) d = dd;
    g_idx[t] = d;
}

// ---------------- 2) sketched weights -> hi/lo, [co][tap*128+ci] ----------------
__global__ void wsk_kernel(const float* __restrict__ w2, const float* __restrict__ ss) {
    int e = blockIdx.x * 256 + threadIdx.x;
    if (e >= CO_ * KTOT) return;
    int ci = e & 127, tap = (e >> 7) % 9, co = e / KTOT;
    int j = co >> 5, d = co & 31;
    float sum = 0.f;
    for (int c = 0; c < C_; ++c) {
        int   ic = g_idx[j * C_ + c];
        float wv = w2[(c * C_ + ci) * 9 + tap];
        sum += (ic == d) ? ss[j * C_ + c] * wv : 0.f;
    }
    __nv_bfloat16 hi = __float2bfloat16(sum);
    g_wh[e] = hi;
    g_wl[e] = __float2bfloat16(sum - __bfloat162float(hi));
}

// ---------------- 3a) zero padded borders of g_xh / g_xl ----------------
__global__ void zero_kernel() {
    int t = blockIdx.x * 256 + threadIdx.x;          // B_ * 260 * 16
    if (t >= B_ * 260 * 16) return;
    int v  = t & 15;
    int pb = (t >> 4) % 260;
    int b  = t / (260 * 16);
    int h, w;
    if (pb < 66)       { h = 0;  w = pb; }
    else if (pb < 132) { h = 65; w = pb - 66; }
    else { int q = pb - 132; h = 1 + (q >> 1); w = (q & 1) * 65; }
    size_t off = (((size_t)b * HP_ + h) * WP_ + w) * C_ + v * 8;
    *(uint4*)(g_xh + off) = make_uint4(0, 0, 0, 0);
    *(uint4*)(g_xl + off) = make_uint4(0, 0, 0, 0);
}

// ---------------- 3b) NCHW fp32 -> padded NHWC bf16 hi/lo ----------------
__global__ __launch_bounds__(256) void xT_kernel(const float* __restrict__ x) {
    __shared__ float sm[128 * 65];
    const int t = threadIdx.x, h = blockIdx.x, b = blockIdx.y;
    const float* xp = x + (size_t)b * C_ * HW_ + h * W_;
#pragma unroll
    for (int k = 0; k < 32; ++k) {
        int idx = (k << 8) + t;
        int c = idx >> 6, w = idx & 63;
        sm[c * 65 + w] = xp[(size_t)c * HW_ + w];
    }
    __syncthreads();
    size_t dbase = (((size_t)b * HP_ + h + 1) * WP_ + 1) * C_;
#pragma unroll
    for (int k = 0; k < 16; ++k) {
        int idx = (k << 8) + t;
        int w = idx >> 6, c2 = idx & 63;
        float f0 = sm[(2 * c2) * 65 + w];
        float f1 = sm[(2 * c2 + 1) * 65 + w];
        __nv_bfloat162 hh = __floats2bfloat162_rn(f0, f1);
        float r0 = f0 - __bfloat162float(hh.x);
        float r1 = f1 - __bfloat162float(hh.y);
        __nv_bfloat162 ll = __floats2bfloat162_rn(r0, r1);
        size_t o = dbase + (size_t)w * C_ + 2 * c2;
        *(unsigned*)(g_xh + o) = *(unsigned*)&hh;
        *(unsigned*)(g_xl + o) = *(unsigned*)&ll;
    }
}

// ---------------- 4) mma.sync conv: M=96 co, N=128 pixels, K=18x64 x 3 terms ----------------
// SMEM layout (dynamic, 64512 B): sAh[96][72] sAl[96][72] sBh[128][72] sBl[128][72]
// 72-elem (144 B) row pitch -> conflict-free ldmatrix (36r mod 32 distinct over 8 rows)
__global__ __launch_bounds__(256, 2)
void conv_mma_kernel(const float* __restrict__ ss) {
    extern __shared__ __nv_bfloat16 dsm[];
    __nv_bfloat16* sAh = dsm;                 // 96*72
    __nv_bfloat16* sAl = sAh + 96 * 72;
    __nv_bfloat16* sBh = sAl + 96 * 72;       // 128*72
    __nv_bfloat16* sBl = sBh + 128 * 72;

    const int tid = threadIdx.x, warp = tid >> 5, lane = tid & 31;
    const int b = blockIdx.y, h0 = blockIdx.x << 1;   // 2 output rows per CTA
    const int m0 = (warp >> 2) * 48;                  // 2 warps in M: 48 rows each
    const int n0 = (warp & 3) * 32;                   // 4 warps in N: 32 pixels each

    const uint32_t aAh = smem_u32(sAh), aAl = smem_u32(sAl);
    const uint32_t aBh = smem_u32(sBh), aBl = smem_u32(sBl);

    // ldmatrix per-lane offsets
    uint32_t a_off[3];
#pragma unroll
    for (int ti = 0; ti < 3; ++ti)
        a_off[ti] = (uint32_t)((m0 + ti * 16 + (lane & 15)) * 144 + (lane >> 4) * 16);
    uint32_t b_off[2];
    {
        int o = lane >> 3;
#pragma unroll
        for (int u = 0; u < 2; ++u) {
            int pix = n0 + u * 16 + (o >> 1) * 8 + (lane & 7);
            b_off[u] = (uint32_t)(pix * 144 + (o & 1) * 16);
        }
    }

    float acc[3][4][4];
#pragma unroll
    for (int ti = 0; ti < 3; ++ti)
#pragma unroll
        for (int tj = 0; tj < 4; ++tj)
#pragma unroll
            for (int v = 0; v < 4; ++v) acc[ti][tj][v] = 0.f;

#pragma unroll 1
    for (int chunk = 0; chunk < 18; ++chunk) {
        const int tap = chunk >> 1, half = chunk & 1;
        const int kh = tap / 3, kw = tap - kh * 3;
        const int koff = tap * 128 + half * 64;
        const __nv_bfloat16* wh = g_wh + koff;
        const __nv_bfloat16* wl = g_wl + koff;
        const size_t xoff = (((size_t)b * HP_ + h0 + kh) * WP_ + kw) * C_ + half * 64;
        const __nv_bfloat16* xh = g_xh + xoff;
        const __nv_bfloat16* xl = g_xl + xoff;

        __syncthreads();
        // stage A: 96 rows x 64 ci (3 uint4 per thread, hi and lo)
#pragma unroll
        for (int k = 0; k < 3; ++k) {
            int g = tid + (k << 8);
            int row = g >> 3, sub = g & 7;
            *(uint4*)(sAh + row * 72 + sub * 8) = *(const uint4*)(wh + (size_t)row * KTOT + sub * 8);
            *(uint4*)(sAl + row * 72 + sub * 8) = *(const uint4*)(wl + (size_t)row * KTOT + sub * 8);
        }
        // stage B: 128 pixel rows x 64 ci (4 uint4 per thread, hi and lo)
#pragma unroll
        for (int k = 0; k < 4; ++k) {
            int g = tid + (k << 8);
            int n = g >> 3, sub = g & 7;
            int r = n >> 6, wn = n & 63;
            size_t so = ((size_t)r * WP_ + wn) * C_ + sub * 8;
            *(uint4*)(sBh + n * 72 + sub * 8) = *(const uint4*)(xh + so);
            *(uint4*)(sBl + n * 72 + sub * 8) = *(const uint4*)(xl + so);
        }
        __syncthreads();

#pragma unroll
        for (int s = 0; s < 4; ++s) {
            uint32_t ah[3][4], al[3][4], bh[8], bl[8];
#pragma unroll
            for (int ti = 0; ti < 3; ++ti) {
                ldsm4(ah[ti], aAh + a_off[ti] + s * 32);
                ldsm4(al[ti], aAl + a_off[ti] + s * 32);
            }
#pragma unroll
            for (int u = 0; u < 2; ++u) {
                ldsm4(&bh[u * 4], aBh + b_off[u] + s * 32);
                ldsm4(&bl[u * 4], aBl + b_off[u] + s * 32);
            }
#pragma unroll
            for (int ti = 0; ti < 3; ++ti)
#pragma unroll
                for (int tj = 0; tj < 4; ++tj) {
                    mma16816(acc[ti][tj], ah[ti], &bh[tj * 2]);  // Wh * Xh
                    mma16816(acc[ti][tj], al[ti], &bh[tj * 2]);  // Wl * Xh
                    mma16816(acc[ti][tj], ah[ti], &bl[tj * 2]);  // Wh * Xl
                }
        }
    }

    // ---- accumulators -> SMEM yt[96][132] (reuse staging smem) ----
    __syncthreads();
    float* yt = (float*)dsm;
#pragma unroll
    for (int ti = 0; ti < 3; ++ti)
#pragma unroll
        for (int tj = 0; tj < 4; ++tj) {
            int row = m0 + ti * 16 + (lane >> 2);
            int col = n0 + tj * 8 + (lane & 3) * 2;
            *(float2*)&yt[row * 132 + col]       = make_float2(acc[ti][tj][0], acc[ti][tj][1]);
            *(float2*)&yt[(row + 8) * 132 + col] = make_float2(acc[ti][tj][2], acc[ti][tj][3]);
        }
    __syncthreads();

    // ---- unsketch (gather + sign) + median-of-3, coalesced g_med store ----
    const int sp = tid & 127, cg = tid >> 7;
    const int hh = h0 + (sp >> 6), wn = sp & 63;
    float* mbase = g_med + ((size_t)b * C_) * HW_ + hh * W_ + wn;
#pragma unroll 1
    for (int cc = 0; cc < 64; ++cc) {
        int c = (cg << 6) + cc;
        int i0 = g_idx[c], i1 = g_idx[C_ + c], i2 = g_idx[2 * C_ + c];
        float s0 = ss[c], s1 = ss[C_ + c], s2 = ss[2 * C_ + c];
        float v0 = s0 * yt[i0 * 132 + sp];
        float v1 = s1 * yt[(32 + i1) * 132 + sp];
        float v2 = s2 * yt[(64 + i2) * 132 + sp];
        float mx = fmaxf(v0, v1), mn = fminf(v0, v1);
        mbase[(size_t)c * HW_] = fmaxf(mn, fminf(mx, v2));
    }
}

// ---------------- 5) BN stats, two-stage ----------------
__global__ void stats1_kernel() {
    const int c = blockIdx.x, q = blockIdx.y, tid = threadIdx.x;
    float s = 0.f, qq = 0.f;
    for (int bb = q * 4; bb < q * 4 + 4; ++bb) {
        const float4* p = (const float4*)(g_med + ((size_t)bb * C_ + c) * HW_);
        for (int i = tid; i < HW_ / 4; i += 256) {
            float4 v = p[i];
            s += v.x + v.y + v.z + v.w;
            qq = fmaf(v.x, v.x, fmaf(v.y, v.y, fmaf(v.z, v.z, fmaf(v.w, v.w, qq))));
        }
    }
    __shared__ float rs[8], rq[8];
#pragma unroll
    for (int o = 16; o; o >>= 1) {
        s  += __shfl_down_sync(0xffffffffu, s,  o);
        qq += __shfl_down_sync(0xffffffffu, qq, o);
    }
    if ((tid & 31) == 0) { rs[tid >> 5] = s; rq[tid >> 5] = qq; }
    __syncthreads();
    if (tid == 0) {
        float S = 0.f, Q = 0.f;
        for (int i = 0; i < 8; ++i) { S += rs[i]; Q += rq[i]; }
        g_part[c * 8 + q] = make_float2(S, Q);
    }
}
__global__ void stats2_kernel(const float* __restrict__ gamma2,
                              const float* __restrict__ beta2) {
    int c = threadIdx.x;
    float S = 0.f, Q = 0.f;
    for (int q = 0; q < 8; ++q) { float2 p = g_part[c * 8 + q]; S += p.x; Q += p.y; }
    const float invn = 1.f / (float)(B_ * HW_);
    float mean  = S * invn;
    float var   = Q * invn - mean * mean;
    float scale = gamma2[c] * rsqrtf(var + 1e-5f);
    g_sb[c] = make_float2(scale, beta2[c] - mean * scale);
}

// ---------------- 6) normalize + ReLU + residual ----------------
__global__ void out_kernel(const float* __restrict__ x, float* __restrict__ out) {
    size_t i = ((size_t)blockIdx.x * 256 + threadIdx.x) << 2;
    int c = (int)((i >> 12) & 127);
    float2 sb = g_sb[c];
    float4 m  = *(const float4*)&g_med[i];
    float4 xv = *(const float4*)&x[i];
    float4 o;
    o.x = fmaxf(fmaf(m.x, sb.x, sb.y), 0.f) + xv.x;
    o.y = fmaxf(fmaf(m.y, sb.x, sb.y), 0.f) + xv.y;
    o.z = fmaxf(fmaf(m.z, sb.x, sb.y), 0.f) + xv.z;
    o.w = fmaxf(fmaf(m.w, sb.x, sb.y), 0.f) + xv.w;
    *(float4*)&out[i] = o;
}

// ---------------- launch ----------------
extern "C" void kernel_launch(void* const* d_in, const int* in_sizes, int n_in,
                              void* d_out, int out_size) {
    (void)in_sizes; (void)n_in; (void)out_size;
    const float* x      = (const float*)d_in[0];
    // d_in[1] = w1, d_in[3] = gamma1, d_in[4] = beta1: unused (reference discards out1)
    const float* w2     = (const float*)d_in[2];
    const float* gamma2 = (const float*)d_in[5];
    const float* beta2  = (const float*)d_in[6];
    const float* hs     = (const float*)d_in[7];
    const float* ss     = (const float*)d_in[8];
    float* out = (float*)d_out;

    const int DSMEM = (96 * 72 * 2 + 128 * 72 * 2) * 2;   // 64512 B
    cudaFuncSetAttribute(conv_mma_kernel, cudaFuncAttributeMaxDynamicSharedMemorySize, DSMEM);

    idx_kernel<<<2, 256>>>(hs);
    wsk_kernel<<<(CO_ * KTOT + 255) / 256, 256>>>(w2, ss);
    zero_kernel<<<(B_ * 260 * 16 + 255) / 256, 256>>>();
    xT_kernel<<<dim3(H_, B_), 256>>>(x);
    conv_mma_kernel<<<dim3(H_ / 2, B_), 256, DSMEM>>>(ss);
    stats1_kernel<<<dim3(C_, 8), 256>>>();
    stats2_kernel<<<1, C_>>>(gamma2, beta2);
    out_kernel<<<(B_ * C_ * HW_) / 1024, 256>>>(x, out);
}